// round 16
// baseline (speedup 1.0000x reference)
#include <cuda_runtime.h>
#include <cuda_bf16.h>
#include <cstdint>

// ---------------------------------------------------------------------------
// NonLocalBlock: B=8, C=256, Ci=128, H=W=64, N=4096, M=1024
// ALL GEMMs mma.sync bf16x3. attn: warp-specialized S-crew / Y-crew pipeline.
// ---------------------------------------------------------------------------

#define NB 8
#define CC 256
#define CI 128
#define NN 4096
#define MM 1024

typedef unsigned long long u64;

__device__ __forceinline__ float exp_s(float s) {
    float r;
    float t = fmaf(s, 1.4426950408889634f, -28.853900817779268f);
    asm("ex2.approx.f32 %0, %1;" : "=f"(r) : "f"(t));
    return r;
}

__device__ __forceinline__ uint32_t smem_u32(const void* p) {
    uint32_t a;
    asm("{ .reg .u64 t; cvta.to.shared.u64 t, %1; cvt.u32.u64 %0, t; }" : "=r"(a) : "l"(p));
    return a;
}
__device__ __forceinline__ void ldm4(uint32_t* r, uint32_t addr) {
    asm volatile("ldmatrix.sync.aligned.m8n8.x4.shared.b16 {%0,%1,%2,%3}, [%4];"
        : "=r"(r[0]), "=r"(r[1]), "=r"(r[2]), "=r"(r[3]) : "r"(addr));
}
__device__ __forceinline__ void mma_bf16(float* c, const uint32_t* a,
                                         uint32_t b0, uint32_t b1) {
    asm volatile(
        "mma.sync.aligned.m16n8k16.row.col.f32.bf16.bf16.f32 "
        "{%0,%1,%2,%3}, {%4,%5,%6,%7}, {%8,%9}, {%0,%1,%2,%3};"
        : "+f"(c[0]), "+f"(c[1]), "+f"(c[2]), "+f"(c[3])
        : "r"(a[0]), "r"(a[1]), "r"(a[2]), "r"(a[3]), "r"(b0), "r"(b1));
}
__device__ __forceinline__ void cpa16(uint32_t dst, const void* src) {
    asm volatile("cp.async.cg.shared.global [%0], [%1], 16;" :: "r"(dst), "l"(src));
}
#define CPA_COMMIT() asm volatile("cp.async.commit_group;" ::: "memory")
#define CPA_WAIT0()  asm volatile("cp.async.wait_group 0;" ::: "memory")
#define CPA_WAIT1()  asm volatile("cp.async.wait_group 1;" ::: "memory")

__device__ __forceinline__ uint32_t pack_bf16x2(float a, float b) {
    __nv_bfloat16 ha = __float2bfloat16_rn(a), hb = __float2bfloat16_rn(b);
    return ((uint32_t)__bfloat16_as_ushort(hb) << 16) | (uint32_t)__bfloat16_as_ushort(ha);
}

// ----------------------------- scratch ------------------------------------
__device__ uint16_t g_thTH[NB * NN * CI];   // theta split [b][n][ci]
__device__ uint16_t g_thTL[NB * NN * CI];
__device__ uint16_t g_phiH[NB * MM * CI];   // pooled phi split [b][m][ci]
__device__ uint16_t g_phiL[NB * MM * CI];
__device__ uint16_t g_gHa [NB * CI * MM];   // pooled g split [b][ci][m]
__device__ uint16_t g_gLa [NB * CI * MM];
__device__ uint16_t g_xTH [NB * NN * CC];   // x^T split [b][n][c]
__device__ uint16_t g_xTL [NB * NN * CC];
__device__ uint16_t g_yTH [NB * NN * CI];   // y^T split [b][n][ci]
__device__ uint16_t g_yTL [NB * NN * CI];
__device__ uint16_t g_wsH [131072];         // tw|pw|gw (3x32768) then Ww (32768)
__device__ uint16_t g_wsL [131072];
__device__ float g_z    [NB * CC * NN];
__device__ float g_psum [CC * 256];
__device__ float g_psumsq[CC * 256];
__device__ float g_bna[CC], g_bnb[CC];

// ---------------------------------------------------------------------------
__global__ __launch_bounds__(256) void xsplit_kernel(const float* __restrict__ src)
{
    __shared__ float t[32][33];
    int b = blockIdx.z, c0 = blockIdx.y * 32, n0 = blockIdx.x * 32;
    int tid = threadIdx.x;
    int cl = tid >> 3, ng = (tid & 7) * 4;
    float4 v = *(const float4*)&src[((u64)b * CC + c0 + cl) * NN + n0 + ng];
    t[cl][ng] = v.x; t[cl][ng + 1] = v.y; t[cl][ng + 2] = v.z; t[cl][ng + 3] = v.w;
    __syncthreads();
    int nl = tid >> 3, cg = (tid & 7) * 4;
    uint16_t hs[4], ls[4];
#pragma unroll
    for (int e = 0; e < 4; e++) {
        float val = t[cg + e][nl];
        __nv_bfloat16 h = __float2bfloat16_rn(val);
        __nv_bfloat16 l = __float2bfloat16_rn(val - __bfloat162float(h));
        hs[e] = __bfloat16_as_ushort(h); ls[e] = __bfloat16_as_ushort(l);
    }
    u64 di = ((u64)b * NN + n0 + nl) * CC + c0 + cg;
    *(uint2*)&g_xTH[di] = *(uint2*)hs;
    *(uint2*)&g_xTL[di] = *(uint2*)ls;
}

// ---------------------------------------------------------------------------
__global__ __launch_bounds__(256) void wsplit_kernel(
    const float* __restrict__ tw, const float* __restrict__ pw,
    const float* __restrict__ gw, const float* __restrict__ Ww)
{
    int idx = blockIdx.x * 256 + threadIdx.x;
    const float* src; int off;
    if (idx < 32768)       { src = tw; off = idx; }
    else if (idx < 65536)  { src = pw; off = idx - 32768; }
    else if (idx < 98304)  { src = gw; off = idx - 65536; }
    else                   { src = Ww; off = idx - 98304; }
    float v = src[off];
    __nv_bfloat16 h = __float2bfloat16_rn(v);
    __nv_bfloat16 l = __float2bfloat16_rn(v - __bfloat162float(h));
    g_wsH[idx] = __bfloat16_as_ushort(h);
    g_wsL[idx] = __bfloat16_as_ushort(l);
}

// ---------------------------------------------------------------------------
// proj_mma: K=256 in 4 chunks of 64; 2 CTAs/SM. (validated R12/R13)
// ---------------------------------------------------------------------------
#define PADB2 144
#define TILE2 18432
#define PRJ_SMEM (4 * TILE2)

__global__ __launch_bounds__(256, 2) void proj_mma_kernel(
    const float* __restrict__ tb, const float* __restrict__ pb,
    const float* __restrict__ gb)
{
    extern __shared__ char smem[];
    uint32_t sb = smem_u32(smem);
    const uint32_t O_AH = 0, O_AL = TILE2, O_BH = 2 * TILE2, O_BL = 3 * TILE2;
    int b = blockIdx.z, pj = blockIdx.y, n0 = blockIdx.x * 128;
    int tid = threadIdx.x, lane = tid & 31, wid = tid >> 5;
    int wrow = wid * 16, qr = lane >> 2, qc = lane & 3;

    const uint16_t* wH = g_wsH + pj * 32768;
    const uint16_t* wL = g_wsL + pj * 32768;
    const float* bias = (pj == 0) ? tb : (pj == 1) ? pb : gb;

    uint32_t a_row = (uint32_t)(wrow + (lane & 15));
    uint32_t a_seg = (uint32_t)((lane >> 4) << 4);
    uint32_t b_rlane = (uint32_t)(lane & 7);
    uint32_t b_seg = (uint32_t)((lane >> 3) << 4);

    float Dacc[16][4];
#pragma unroll
    for (int t = 0; t < 16; t++) { Dacc[t][0] = Dacc[t][1] = Dacc[t][2] = Dacc[t][3] = 0.f; }

    for (int kc = 0; kc < 4; kc++) {
#pragma unroll
        for (int j = 0; j < 4; j++) {
            int id = tid + j * 256;
            int row = id >> 3, seg = id & 7;
            uint32_t d = row * PADB2 + seg * 16;
            int wsrc = row * 256 + kc * 64 + seg * 8;
            u64 xsrc = ((u64)b * NN + n0 + row) * CC + kc * 64 + seg * 8;
            cpa16(sb + O_AH + d, &wH[wsrc]);
            cpa16(sb + O_AL + d, &wL[wsrc]);
            cpa16(sb + O_BH + d, &g_xTH[xsrc]);
            cpa16(sb + O_BL + d, &g_xTL[xsrc]);
        }
        CPA_COMMIT(); CPA_WAIT0();
        __syncthreads();

#pragma unroll
        for (int kt = 0; kt < 4; kt += 2) {
            uint32_t aH[8], aL[8];
            uint32_t abase = a_row * PADB2 + kt * 32 + a_seg;
            ldm4(aH + 0, sb + O_AH + abase);
            ldm4(aH + 4, sb + O_AH + abase + 32);
            ldm4(aL + 0, sb + O_AL + abase);
            ldm4(aL + 4, sb + O_AL + abase + 32);
#pragma unroll
            for (int mt = 0; mt < 16; mt++) {
                uint32_t bH[4], bL[4];
                uint32_t bbase = (mt * 8 + b_rlane) * PADB2 + kt * 32 + b_seg;
                ldm4(bH, sb + O_BH + bbase);
                ldm4(bL, sb + O_BL + bbase);
                mma_bf16(Dacc[mt], aH + 0, bH[0], bH[1]);
                mma_bf16(Dacc[mt], aH + 0, bL[0], bL[1]);
                mma_bf16(Dacc[mt], aL + 0, bH[0], bH[1]);
                mma_bf16(Dacc[mt], aH + 4, bH[2], bH[3]);
                mma_bf16(Dacc[mt], aH + 4, bL[2], bL[3]);
                mma_bf16(Dacc[mt], aL + 4, bH[2], bH[3]);
            }
        }
        __syncthreads();
    }

    int o0 = wrow + qr;
    float bv0 = bias[o0], bv1 = bias[o0 + 8];

    if (pj == 0) {
#pragma unroll
        for (int mt = 0; mt < 16; mt++) {
            int n = n0 + mt * 8 + qc * 2;
            float v0 = Dacc[mt][0] + bv0;
            float v1 = Dacc[mt][1] + bv0;
            float v2 = Dacc[mt][2] + bv1;
            float v3 = Dacc[mt][3] + bv1;
            u64 r0 = ((u64)b * NN + n) * CI + o0;
            u64 r1 = r0 + CI;
            __nv_bfloat16 h;
            h = __float2bfloat16_rn(v0);
            g_thTH[r0] = __bfloat16_as_ushort(h);
            g_thTL[r0] = __bfloat16_as_ushort(__float2bfloat16_rn(v0 - __bfloat162float(h)));
            h = __float2bfloat16_rn(v2);
            g_thTH[r0 + 8] = __bfloat16_as_ushort(h);
            g_thTL[r0 + 8] = __bfloat16_as_ushort(__float2bfloat16_rn(v2 - __bfloat162float(h)));
            h = __float2bfloat16_rn(v1);
            g_thTH[r1] = __bfloat16_as_ushort(h);
            g_thTL[r1] = __bfloat16_as_ushort(__float2bfloat16_rn(v1 - __bfloat162float(h)));
            h = __float2bfloat16_rn(v3);
            g_thTH[r1 + 8] = __bfloat16_as_ushort(h);
            g_thTL[r1 + 8] = __bfloat16_as_ushort(__float2bfloat16_rn(v3 - __bfloat162float(h)));
        }
    } else {
        uint16_t* dH = (pj == 1) ? g_phiH : g_gHa;
        uint16_t* dL = (pj == 1) ? g_phiL : g_gLa;
#pragma unroll
        for (int mt2 = 0; mt2 < 8; mt2++) {
            int m = blockIdx.x * 32 + mt2 * 4 + qc;
            float p0 = fmaxf(fmaxf(Dacc[mt2][0], Dacc[mt2][1]),
                             fmaxf(Dacc[mt2 + 8][0], Dacc[mt2 + 8][1])) + bv0;
            float p1 = fmaxf(fmaxf(Dacc[mt2][2], Dacc[mt2][3]),
                             fmaxf(Dacc[mt2 + 8][2], Dacc[mt2 + 8][3])) + bv1;
            __nv_bfloat16 h0 = __float2bfloat16_rn(p0);
            __nv_bfloat16 l0 = __float2bfloat16_rn(p0 - __bfloat162float(h0));
            __nv_bfloat16 h1 = __float2bfloat16_rn(p1);
            __nv_bfloat16 l1 = __float2bfloat16_rn(p1 - __bfloat162float(h1));
            u64 i0, i1;
            if (pj == 1) { i0 = ((u64)b * MM + m) * CI + o0; i1 = i0 + 8; }
            else         { i0 = ((u64)b * CI + o0) * MM + m; i1 = i0 + (u64)8 * MM; }
            dH[i0] = __bfloat16_as_ushort(h0); dL[i0] = __bfloat16_as_ushort(l0);
            dH[i1] = __bfloat16_as_ushort(h1); dL[i1] = __bfloat16_as_ushort(l1);
        }
    }
}

// ---------------------------------------------------------------------------
// K2: attention, warp-specialized. CTA = (b, 64 n). m-chunks of 64, 16 chunks.
// Warps 0-3 (S crew): S(i)=theta.phi^T (16n x 64m each), exp -> P(i).
// Warps 4-7 (Y crew): Y(i-1)+=g.P^T (32ci x 64n each).
// smem: TH/TL [64][272] | PHI x2 (H,L [64][272]) | G x2 (H,L [128][144])
//       | P x2 (H,L [64][144]) | inv[64]
// ---------------------------------------------------------------------------
#define AT_TH   0
#define AT_TL   17408
#define AT_PHI  34816
#define AT_G    104448
#define AT_P    178176
#define AT_INV  215040
#define ATT_SMEM 215296

__global__ __launch_bounds__(256, 1) void attn_mma_kernel()
{
    extern __shared__ char smem[];
    uint32_t sb = smem_u32(smem);
    int b = blockIdx.y, n0 = blockIdx.x * 64;
    int tid = threadIdx.x;
    int lane = tid & 31, wid = tid >> 5;
    int qr = lane >> 2, qc = lane & 3;

    auto phiH = [&](int bf) { return sb + AT_PHI + bf * 34816; };
    auto phiL = [&](int bf) { return sb + AT_PHI + bf * 34816 + 17408; };
    auto gH   = [&](int bf) { return sb + AT_G + bf * 36864; };
    auto gL   = [&](int bf) { return sb + AT_G + bf * 36864 + 18432; };
    auto pH   = [&](int bf) { return sb + AT_P + bf * 18432; };
    auto pL   = [&](int bf) { return sb + AT_P + bf * 18432 + 9216; };

    auto load_phi = [&](int mc, int bf) {
#pragma unroll
        for (int j = 0; j < 4; j++) {
            int id = tid + j * 256;
            int row = id >> 4, seg = id & 15;   // 64 rows x 16 segs
            int src = (b * MM + mc * 64 + row) * CI + seg * 8;
            uint32_t d = row * 272 + seg * 16;
            cpa16(phiH(bf) + d, &g_phiH[src]);
            cpa16(phiL(bf) + d, &g_phiL[src]);
        }
    };
    auto load_g = [&](int mc, int bf) {
#pragma unroll
        for (int j = 0; j < 4; j++) {
            int id = tid + j * 256;
            int row = id >> 3, seg = id & 7;    // 128 rows x 8 segs
            int src = (b * CI + row) * MM + mc * 64 + seg * 8;
            uint32_t d = row * 144 + seg * 16;
            cpa16(gH(bf) + d, &g_gHa[src]);
            cpa16(gL(bf) + d, &g_gLa[src]);
        }
    };

    // prologue: theta + phi(0)->buf0 + g(0)->buf0
#pragma unroll
    for (int j = 0; j < 4; j++) {
        int id = tid + j * 256;
        int row = id >> 4, seg = id & 15;
        u64 src = ((u64)b * NN + n0 + row) * CI + seg * 8;
        uint32_t d = row * 272 + seg * 16;
        cpa16(sb + AT_TH + d, &g_thTH[src]);
        cpa16(sb + AT_TL + d, &g_thTL[src]);
    }
    load_phi(0, 0);
    load_g(0, 0);
    CPA_COMMIT();
    CPA_WAIT0();
    __syncthreads();

    bool is_s = (wid < 4);
    int sw = wid;         // S crew warp id (0..3)
    int yw = wid - 4;     // Y crew warp id (0..3)

    float Sacc[8][4];     // S crew: 16n x 64m
    float Yacc[2][8][4];  // Y crew: 32ci x 64n
#pragma unroll
    for (int t = 0; t < 8; t++) {
        Sacc[t][0] = Sacc[t][1] = Sacc[t][2] = Sacc[t][3] = 0.f;
        Yacc[0][t][0] = Yacc[0][t][1] = Yacc[0][t][2] = Yacc[0][t][3] = 0.f;
        Yacc[1][t][0] = Yacc[1][t][1] = Yacc[1][t][2] = Yacc[1][t][3] = 0.f;
    }
    float rs0 = 0.f, rs1 = 0.f;

    uint32_t a_seg = (uint32_t)((lane >> 4) << 4);
    uint32_t b_rl = (uint32_t)(lane & 7);
    uint32_t b_seg = (uint32_t)((lane >> 3) << 4);
    uint32_t aS_row = (uint32_t)(sw * 16 + (lane & 15));
    uint32_t aY0 = (uint32_t)(yw * 32 + (lane & 15));
    uint32_t aY1 = aY0 + 16;

    for (int i = 0; i <= 16; i++) {
        int cur = i & 1, prv = cur ^ 1;

        // ---- phase 1: loads(phi i+1) + S(i) [S crew] + Y(i-1) [Y crew] ----
        if (i < 15) { load_phi(i + 1, prv); CPA_COMMIT(); }

        if (is_s && i < 16) {
#pragma unroll
            for (int kt = 0; kt < 8; kt += 2) {
                uint32_t aH[8], aL[8];
                uint32_t abase = aS_row * 272 + kt * 32 + a_seg;
                ldm4(aH + 0, sb + AT_TH + abase);
                ldm4(aH + 4, sb + AT_TH + abase + 32);
                ldm4(aL + 0, sb + AT_TL + abase);
                ldm4(aL + 4, sb + AT_TL + abase + 32);
#pragma unroll
                for (int mt = 0; mt < 8; mt++) {
                    uint32_t bH[4], bL[4];
                    uint32_t bbase = (mt * 8 + b_rl) * 272 + kt * 32 + b_seg;
                    ldm4(bH, phiH(cur) + bbase);
                    ldm4(bL, phiL(cur) + bbase);
                    mma_bf16(Sacc[mt], aH + 0, bH[0], bH[1]);
                    mma_bf16(Sacc[mt], aH + 0, bL[0], bL[1]);
                    mma_bf16(Sacc[mt], aL + 0, bH[0], bH[1]);
                    mma_bf16(Sacc[mt], aH + 4, bH[2], bH[3]);
                    mma_bf16(Sacc[mt], aH + 4, bL[2], bL[3]);
                    mma_bf16(Sacc[mt], aL + 4, bH[2], bH[3]);
                }
            }
        }
        if (!is_s && i > 0) {
#pragma unroll
            for (int kt = 0; kt < 4; kt += 2) {
                uint32_t aH0[8], aL0[8], aH1[8], aL1[8];
                uint32_t ab0 = aY0 * 144 + kt * 32 + a_seg;
                uint32_t ab1 = aY1 * 144 + kt * 32 + a_seg;
                ldm4(aH0 + 0, gH(prv) + ab0); ldm4(aH0 + 4, gH(prv) + ab0 + 32);
                ldm4(aL0 + 0, gL(prv) + ab0); ldm4(aL0 + 4, gL(prv) + ab0 + 32);
                ldm4(aH1 + 0, gH(prv) + ab1); ldm4(aH1 + 4, gH(prv) + ab1 + 32);
                ldm4(aL1 + 0, gL(prv) + ab1); ldm4(aL1 + 4, gL(prv) + ab1 + 32);
#pragma unroll
                for (int nt = 0; nt < 8; nt++) {
                    uint32_t bH[4], bL[4];
                    uint32_t bbase = (nt * 8 + b_rl) * 144 + kt * 32 + b_seg;
                    ldm4(bH, pH(prv) + bbase);
                    ldm4(bL, pL(prv) + bbase);
                    mma_bf16(Yacc[0][nt], aH0 + 0, bH[0], bH[1]);
                    mma_bf16(Yacc[0][nt], aH0 + 0, bL[0], bL[1]);
                    mma_bf16(Yacc[0][nt], aL0 + 0, bH[0], bH[1]);
                    mma_bf16(Yacc[0][nt], aH0 + 4, bH[2], bH[3]);
                    mma_bf16(Yacc[0][nt], aH0 + 4, bL[2], bL[3]);
                    mma_bf16(Yacc[0][nt], aL0 + 4, bH[2], bH[3]);
                    mma_bf16(Yacc[1][nt], aH1 + 0, bH[0], bH[1]);
                    mma_bf16(Yacc[1][nt], aH1 + 0, bL[0], bL[1]);
                    mma_bf16(Yacc[1][nt], aL1 + 0, bH[0], bH[1]);
                    mma_bf16(Yacc[1][nt], aH1 + 4, bH[2], bH[3]);
                    mma_bf16(Yacc[1][nt], aH1 + 4, bL[2], bL[3]);
                    mma_bf16(Yacc[1][nt], aL1 + 4, bH[2], bH[3]);
                }
            }
        }
        __syncthreads();

        // ---- phase 2: exp(i)->P(cur) [S crew] + loads(g i+1) + wait ----
        if (i < 15) { load_g(i + 1, prv); CPA_COMMIT(); }
        if (is_s && i < 16) {
            int r0 = sw * 16 + qr, r1 = r0 + 8;
#pragma unroll
            for (int mt = 0; mt < 8; mt++) {
                float e0 = exp_s(Sacc[mt][0]);
                float e1 = exp_s(Sacc[mt][1]);
                float e2 = exp_s(Sacc[mt][2]);
                float e3 = exp_s(Sacc[mt][3]);
                rs0 += e0 + e1; rs1 += e2 + e3;
                float h0 = __bfloat162float(__float2bfloat16_rn(e0));
                float h1 = __bfloat162float(__float2bfloat16_rn(e1));
                float h2 = __bfloat162float(__float2bfloat16_rn(e2));
                float h3 = __bfloat162float(__float2bfloat16_rn(e3));
                int m2 = (mt * 8 + qc * 2) * 2;
                uint32_t off0 = r0 * 144 + m2;
                uint32_t off1 = r1 * 144 + m2;
                *(uint32_t*)(smem + (pH(cur) - sb) + off0) = pack_bf16x2(h0, h1);
                *(uint32_t*)(smem + (pH(cur) - sb) + off1) = pack_bf16x2(h2, h3);
                *(uint32_t*)(smem + (pL(cur) - sb) + off0) = pack_bf16x2(e0 - h0, e1 - h1);
                *(uint32_t*)(smem + (pL(cur) - sb) + off1) = pack_bf16x2(e2 - h2, e3 - h3);
                // reset for next chunk
                Sacc[mt][0] = Sacc[mt][1] = Sacc[mt][2] = Sacc[mt][3] = 0.f;
            }
        }
        if (i < 15) { CPA_WAIT1(); } else { CPA_WAIT0(); }
        __syncthreads();
    }

    // ---- rowsums -> inv (S crew; each n-row owned by exactly one lane grp) ----
    float* invs = (float*)(smem + AT_INV);
    if (is_s) {
        rs0 += __shfl_xor_sync(0xffffffffu, rs0, 1);
        rs0 += __shfl_xor_sync(0xffffffffu, rs0, 2);
        rs1 += __shfl_xor_sync(0xffffffffu, rs1, 1);
        rs1 += __shfl_xor_sync(0xffffffffu, rs1, 2);
        if (qc == 0) {
            invs[sw * 16 + qr]     = 1.0f / rs0;
            invs[sw * 16 + qr + 8] = 1.0f / rs1;
        }
    }
    __syncthreads();

    // ---- epilogue (Y crew): normalize, split, store y^T [b][n][ci] ----
    if (!is_s) {
#pragma unroll
        for (int rb = 0; rb < 2; rb++) {
            int ci0 = yw * 32 + rb * 16 + qr;
#pragma unroll
            for (int nt = 0; nt < 8; nt++) {
                int nl2 = nt * 8 + qc * 2;
                float in0 = invs[nl2], in1 = invs[nl2 + 1];
                float y00 = Yacc[rb][nt][0] * in0;
                float y01 = Yacc[rb][nt][1] * in1;
                float y10 = Yacc[rb][nt][2] * in0;
                float y11 = Yacc[rb][nt][3] * in1;
                u64 r0 = ((u64)b * NN + n0 + nl2) * CI + ci0;
                u64 r1 = r0 + CI;
                __nv_bfloat16 h;
                h = __float2bfloat16_rn(y00);
                g_yTH[r0] = __bfloat16_as_ushort(h);
                g_yTL[r0] = __bfloat16_as_ushort(__float2bfloat16_rn(y00 - __bfloat162float(h)));
                h = __float2bfloat16_rn(y10);
                g_yTH[r0 + 8] = __bfloat16_as_ushort(h);
                g_yTL[r0 + 8] = __bfloat16_as_ushort(__float2bfloat16_rn(y10 - __bfloat162float(h)));
                h = __float2bfloat16_rn(y01);
                g_yTH[r1] = __bfloat16_as_ushort(h);
                g_yTL[r1] = __bfloat16_as_ushort(__float2bfloat16_rn(y01 - __bfloat162float(h)));
                h = __float2bfloat16_rn(y11);
                g_yTH[r1 + 8] = __bfloat16_as_ushort(h);
                g_yTL[r1 + 8] = __bfloat16_as_ushort(__float2bfloat16_rn(y11 - __bfloat162float(h)));
            }
        }
    }
}

// ---------------------------------------------------------------------------
// wproj_mma: K=128 in 2 chunks of 64; 2 CTAs/SM. (validated R12/R13)
// ---------------------------------------------------------------------------
__global__ __launch_bounds__(256, 2) void wproj_mma_kernel(
    const float* __restrict__ bias)
{
    extern __shared__ char smem[];
    uint32_t sb = smem_u32(smem);
    const uint32_t O_AH = 0, O_AL = TILE2, O_BH = 2 * TILE2, O_BL = 3 * TILE2;
    int b = blockIdx.z, o0 = blockIdx.y * 128, n0 = blockIdx.x * 128;
    int tid = threadIdx.x, lane = tid & 31, wid = tid >> 5;
    int wrow = wid * 16, qr = lane >> 2, qc = lane & 3;

    uint32_t a_row = (uint32_t)(wrow + (lane & 15));
    uint32_t a_seg = (uint32_t)((lane >> 4) << 4);
    uint32_t b_rlane = (uint32_t)(lane & 7);
    uint32_t b_seg = (uint32_t)((lane >> 3) << 4);

    float Dacc[16][4];
#pragma unroll
    for (int t = 0; t < 16; t++) { Dacc[t][0] = Dacc[t][1] = Dacc[t][2] = Dacc[t][3] = 0.f; }

    for (int kc = 0; kc < 2; kc++) {
#pragma unroll
        for (int j = 0; j < 4; j++) {
            int id = tid + j * 256;
            int row = id >> 3, seg = id & 7;
            uint32_t d = row * PADB2 + seg * 16;
            int wsrc = 98304 + (o0 + row) * 128 + kc * 64 + seg * 8;
            u64 ysrc = ((u64)b * NN + n0 + row) * CI + kc * 64 + seg * 8;
            cpa16(sb + O_AH + d, &g_wsH[wsrc]);
            cpa16(sb + O_AL + d, &g_wsL[wsrc]);
            cpa16(sb + O_BH + d, &g_yTH[ysrc]);
            cpa16(sb + O_BL + d, &g_yTL[ysrc]);
        }
        CPA_COMMIT(); CPA_WAIT0();
        __syncthreads();

#pragma unroll
        for (int kt = 0; kt < 4; kt += 2) {
            uint32_t aH[8], aL[8];
            uint32_t abase = a_row * PADB2 + kt * 32 + a_seg;
            ldm4(aH + 0, sb + O_AH + abase);
            ldm4(aH + 4, sb + O_AH + abase + 32);
            ldm4(aL + 0, sb + O_AL + abase);
            ldm4(aL + 4, sb + O_AL + abase + 32);
#pragma unroll
            for (int mt = 0; mt < 16; mt++) {
                uint32_t bH[4], bL[4];
                uint32_t bbase = (mt * 8 + b_rlane) * PADB2 + kt * 32 + b_seg;
                ldm4(bH, sb + O_BH + bbase);
                ldm4(bL, sb + O_BL + bbase);
                mma_bf16(Dacc[mt], aH + 0, bH[0], bH[1]);
                mma_bf16(Dacc[mt], aH + 0, bL[0], bL[1]);
                mma_bf16(Dacc[mt], aL + 0, bH[0], bH[1]);
                mma_bf16(Dacc[mt], aH + 4, bH[2], bH[3]);
                mma_bf16(Dacc[mt], aH + 4, bL[2], bL[3]);
                mma_bf16(Dacc[mt], aL + 4, bH[2], bH[3]);
            }
        }
        __syncthreads();
    }

    int og0 = o0 + wrow + qr, og1 = og0 + 8;
    float bv0 = bias[og0], bv1 = bias[og1];
    float* ob = g_z + (u64)b * CC * NN;
    float s0 = 0.f, q0 = 0.f, s1 = 0.f, q1 = 0.f;
#pragma unroll
    for (int mt = 0; mt < 16; mt++) {
        int n = n0 + mt * 8 + qc * 2;
        float v0 = Dacc[mt][0] + bv0, v1 = Dacc[mt][1] + bv0;
        float v2 = Dacc[mt][2] + bv1, v3 = Dacc[mt][3] + bv1;
        *(float2*)&ob[(u64)og0 * NN + n] = make_float2(v0, v1);
        *(float2*)&ob[(u64)og1 * NN + n] = make_float2(v2, v3);
        s0 += v0 + v1; q0 += v0 * v0 + v1 * v1;
        s1 += v2 + v3; q1 += v2 * v2 + v3 * v3;
    }
    s0 += __shfl_xor_sync(0xffffffffu, s0, 1);
    s0 += __shfl_xor_sync(0xffffffffu, s0, 2);
    q0 += __shfl_xor_sync(0xffffffffu, q0, 1);
    q0 += __shfl_xor_sync(0xffffffffu, q0, 2);
    s1 += __shfl_xor_sync(0xffffffffu, s1, 1);
    s1 += __shfl_xor_sync(0xffffffffu, s1, 2);
    q1 += __shfl_xor_sync(0xffffffffu, q1, 1);
    q1 += __shfl_xor_sync(0xffffffffu, q1, 2);
    if (qc == 0) {
        int slot = b * 32 + blockIdx.x;
        g_psum  [og0 * 256 + slot] = s0;
        g_psumsq[og0 * 256 + slot] = q0;
        g_psum  [og1 * 256 + slot] = s1;
        g_psumsq[og1 * 256 + slot] = q1;
    }
}

// ---------------------------------------------------------------------------
__global__ void bnfin_kernel(const float* __restrict__ gamma,
                             const float* __restrict__ beta)
{
    int c = threadIdx.x;
    float s = 0.f, s2 = 0.f;
    for (int j = 0; j < 256; j++) { s += g_psum[c * 256 + j]; s2 += g_psumsq[c * 256 + j]; }
    const float inv_n = 1.0f / 32768.0f;
    float mean = s * inv_n;
    float var  = s2 * inv_n - mean * mean;
    float inv  = rsqrtf(var + 1e-5f);
    float a = gamma[c] * inv;
    g_bna[c] = a;
    g_bnb[c] = beta[c] - mean * a;
}

// ---------------------------------------------------------------------------
__global__ __launch_bounds__(256) void final_kernel(
    const float* __restrict__ x, float* __restrict__ out)
{
    int idx = blockIdx.x * 256 + threadIdx.x;
    u64 e = (u64)idx << 2;
    int c = (int)((e >> 12) & 255);
    float4 xv = *(const float4*)(x + e);
    float4 zv = *((const float4*)g_z + idx);
    float a = g_bna[c], bb = g_bnb[c];
    float4 o;
    o.x = fmaf(zv.x, a, bb) + xv.x;
    o.y = fmaf(zv.y, a, bb) + xv.y;
    o.z = fmaf(zv.z, a, bb) + xv.z;
    o.w = fmaf(zv.w, a, bb) + xv.w;
    *(float4*)(out + e) = o;
}

// ---------------------------------------------------------------------------
extern "C" void kernel_launch(void* const* d_in, const int* in_sizes, int n_in,
                              void* d_out, int out_size)
{
    const float* x     = (const float*)d_in[0];
    const float* tw    = (const float*)d_in[1];
    const float* tb    = (const float*)d_in[2];
    const float* pw    = (const float*)d_in[3];
    const float* pb    = (const float*)d_in[4];
    const float* gw    = (const float*)d_in[5];
    const float* gbv   = (const float*)d_in[6];
    const float* Ww    = (const float*)d_in[7];
    const float* Wb    = (const float*)d_in[8];
    const float* gamma = (const float*)d_in[9];
    const float* beta  = (const float*)d_in[10];
    float* out = (float*)d_out;

    cudaFuncSetAttribute(attn_mma_kernel,
                         cudaFuncAttributeMaxDynamicSharedMemorySize, ATT_SMEM);
    cudaFuncSetAttribute(proj_mma_kernel,
                         cudaFuncAttributeMaxDynamicSharedMemorySize, PRJ_SMEM);
    cudaFuncSetAttribute(wproj_mma_kernel,
                         cudaFuncAttributeMaxDynamicSharedMemorySize, PRJ_SMEM);

    xsplit_kernel<<<dim3(128, 8, 8), 256>>>(x);
    wsplit_kernel<<<512, 256>>>(tw, pw, gw, Ww);
    proj_mma_kernel<<<dim3(32, 3, 8), 256, PRJ_SMEM>>>(tb, pb, gbv);
    attn_mma_kernel<<<dim3(64, 8), 256, ATT_SMEM>>>();
    wproj_mma_kernel<<<dim3(32, 2, 8), 256, PRJ_SMEM>>>(Wb);
    bnfin_kernel<<<1, 256>>>(gamma, beta);
    final_kernel<<<8192, 256>>>(x, out);
}

// round 17
// speedup vs baseline: 1.1344x; 1.1344x over previous
#include <cuda_runtime.h>
#include <cuda_bf16.h>
#include <cstdint>

// ---------------------------------------------------------------------------
// NonLocalBlock: B=8, C=256, Ci=128, H=W=64, N=4096, M=1024
// ALL GEMMs mma.sync bf16x3. attn: R12 structure, widened 32-row warp tiles
// (2 A-tiles per B fragment, -33% LDSM).
// ---------------------------------------------------------------------------

#define NB 8
#define CC 256
#define CI 128
#define NN 4096
#define MM 1024

typedef unsigned long long u64;

__device__ __forceinline__ float exp_s(float s) {
    float r;
    float t = fmaf(s, 1.4426950408889634f, -28.853900817779268f);
    asm("ex2.approx.f32 %0, %1;" : "=f"(r) : "f"(t));
    return r;
}

__device__ __forceinline__ uint32_t smem_u32(const void* p) {
    uint32_t a;
    asm("{ .reg .u64 t; cvta.to.shared.u64 t, %1; cvt.u32.u64 %0, t; }" : "=r"(a) : "l"(p));
    return a;
}
__device__ __forceinline__ void ldm4(uint32_t* r, uint32_t addr) {
    asm volatile("ldmatrix.sync.aligned.m8n8.x4.shared.b16 {%0,%1,%2,%3}, [%4];"
        : "=r"(r[0]), "=r"(r[1]), "=r"(r[2]), "=r"(r[3]) : "r"(addr));
}
__device__ __forceinline__ void mma_bf16(float* c, const uint32_t* a,
                                         uint32_t b0, uint32_t b1) {
    asm volatile(
        "mma.sync.aligned.m16n8k16.row.col.f32.bf16.bf16.f32 "
        "{%0,%1,%2,%3}, {%4,%5,%6,%7}, {%8,%9}, {%0,%1,%2,%3};"
        : "+f"(c[0]), "+f"(c[1]), "+f"(c[2]), "+f"(c[3])
        : "r"(a[0]), "r"(a[1]), "r"(a[2]), "r"(a[3]), "r"(b0), "r"(b1));
}
__device__ __forceinline__ void cpa16(uint32_t dst, const void* src) {
    asm volatile("cp.async.cg.shared.global [%0], [%1], 16;" :: "r"(dst), "l"(src));
}
#define CPA_COMMIT() asm volatile("cp.async.commit_group;" ::: "memory")
#define CPA_WAIT0()  asm volatile("cp.async.wait_group 0;" ::: "memory")
#define CPA_WAIT1()  asm volatile("cp.async.wait_group 1;" ::: "memory")

__device__ __forceinline__ uint32_t pack_bf16x2(float a, float b) {
    __nv_bfloat16 ha = __float2bfloat16_rn(a), hb = __float2bfloat16_rn(b);
    return ((uint32_t)__bfloat16_as_ushort(hb) << 16) | (uint32_t)__bfloat16_as_ushort(ha);
}

// ----------------------------- scratch ------------------------------------
__device__ uint16_t g_thTH[NB * NN * CI];   // theta split [b][n][ci]
__device__ uint16_t g_thTL[NB * NN * CI];
__device__ uint16_t g_phiH[NB * MM * CI];   // pooled phi split [b][m][ci]
__device__ uint16_t g_phiL[NB * MM * CI];
__device__ uint16_t g_gHa [NB * CI * MM];   // pooled g split [b][ci][m]
__device__ uint16_t g_gLa [NB * CI * MM];
__device__ uint16_t g_xTH [NB * NN * CC];   // x^T split [b][n][c]
__device__ uint16_t g_xTL [NB * NN * CC];
__device__ uint16_t g_yTH [NB * NN * CI];   // y^T split [b][n][ci]
__device__ uint16_t g_yTL [NB * NN * CI];
__device__ uint16_t g_wsH [131072];         // tw|pw|gw (3x32768) then Ww (32768)
__device__ uint16_t g_wsL [131072];
__device__ float g_z    [NB * CC * NN];
__device__ float g_psum [CC * 256];
__device__ float g_psumsq[CC * 256];
__device__ float g_bna[CC], g_bnb[CC];

// ---------------------------------------------------------------------------
__global__ __launch_bounds__(256) void xsplit_kernel(const float* __restrict__ src)
{
    __shared__ float t[32][33];
    int b = blockIdx.z, c0 = blockIdx.y * 32, n0 = blockIdx.x * 32;
    int tid = threadIdx.x;
    int cl = tid >> 3, ng = (tid & 7) * 4;
    float4 v = *(const float4*)&src[((u64)b * CC + c0 + cl) * NN + n0 + ng];
    t[cl][ng] = v.x; t[cl][ng + 1] = v.y; t[cl][ng + 2] = v.z; t[cl][ng + 3] = v.w;
    __syncthreads();
    int nl = tid >> 3, cg = (tid & 7) * 4;
    uint16_t hs[4], ls[4];
#pragma unroll
    for (int e = 0; e < 4; e++) {
        float val = t[cg + e][nl];
        __nv_bfloat16 h = __float2bfloat16_rn(val);
        __nv_bfloat16 l = __float2bfloat16_rn(val - __bfloat162float(h));
        hs[e] = __bfloat16_as_ushort(h); ls[e] = __bfloat16_as_ushort(l);
    }
    u64 di = ((u64)b * NN + n0 + nl) * CC + c0 + cg;
    *(uint2*)&g_xTH[di] = *(uint2*)hs;
    *(uint2*)&g_xTL[di] = *(uint2*)ls;
}

// ---------------------------------------------------------------------------
__global__ __launch_bounds__(256) void wsplit_kernel(
    const float* __restrict__ tw, const float* __restrict__ pw,
    const float* __restrict__ gw, const float* __restrict__ Ww)
{
    int idx = blockIdx.x * 256 + threadIdx.x;
    const float* src; int off;
    if (idx < 32768)       { src = tw; off = idx; }
    else if (idx < 65536)  { src = pw; off = idx - 32768; }
    else if (idx < 98304)  { src = gw; off = idx - 65536; }
    else                   { src = Ww; off = idx - 98304; }
    float v = src[off];
    __nv_bfloat16 h = __float2bfloat16_rn(v);
    __nv_bfloat16 l = __float2bfloat16_rn(v - __bfloat162float(h));
    g_wsH[idx] = __bfloat16_as_ushort(h);
    g_wsL[idx] = __bfloat16_as_ushort(l);
}

// ---------------------------------------------------------------------------
// proj_mma: K=256 in 4 chunks of 64; 2 CTAs/SM. (validated R12)
// ---------------------------------------------------------------------------
#define PADB2 144
#define TILE2 18432
#define PRJ_SMEM (4 * TILE2)

__global__ __launch_bounds__(256, 2) void proj_mma_kernel(
    const float* __restrict__ tb, const float* __restrict__ pb,
    const float* __restrict__ gb)
{
    extern __shared__ char smem[];
    uint32_t sb = smem_u32(smem);
    const uint32_t O_AH = 0, O_AL = TILE2, O_BH = 2 * TILE2, O_BL = 3 * TILE2;
    int b = blockIdx.z, pj = blockIdx.y, n0 = blockIdx.x * 128;
    int tid = threadIdx.x, lane = tid & 31, wid = tid >> 5;
    int wrow = wid * 16, qr = lane >> 2, qc = lane & 3;

    const uint16_t* wH = g_wsH + pj * 32768;
    const uint16_t* wL = g_wsL + pj * 32768;
    const float* bias = (pj == 0) ? tb : (pj == 1) ? pb : gb;

    uint32_t a_row = (uint32_t)(wrow + (lane & 15));
    uint32_t a_seg = (uint32_t)((lane >> 4) << 4);
    uint32_t b_rlane = (uint32_t)(lane & 7);
    uint32_t b_seg = (uint32_t)((lane >> 3) << 4);

    float Dacc[16][4];
#pragma unroll
    for (int t = 0; t < 16; t++) { Dacc[t][0] = Dacc[t][1] = Dacc[t][2] = Dacc[t][3] = 0.f; }

    for (int kc = 0; kc < 4; kc++) {
#pragma unroll
        for (int j = 0; j < 4; j++) {
            int id = tid + j * 256;
            int row = id >> 3, seg = id & 7;
            uint32_t d = row * PADB2 + seg * 16;
            int wsrc = row * 256 + kc * 64 + seg * 8;
            u64 xsrc = ((u64)b * NN + n0 + row) * CC + kc * 64 + seg * 8;
            cpa16(sb + O_AH + d, &wH[wsrc]);
            cpa16(sb + O_AL + d, &wL[wsrc]);
            cpa16(sb + O_BH + d, &g_xTH[xsrc]);
            cpa16(sb + O_BL + d, &g_xTL[xsrc]);
        }
        CPA_COMMIT(); CPA_WAIT0();
        __syncthreads();

#pragma unroll
        for (int kt = 0; kt < 4; kt += 2) {
            uint32_t aH[8], aL[8];
            uint32_t abase = a_row * PADB2 + kt * 32 + a_seg;
            ldm4(aH + 0, sb + O_AH + abase);
            ldm4(aH + 4, sb + O_AH + abase + 32);
            ldm4(aL + 0, sb + O_AL + abase);
            ldm4(aL + 4, sb + O_AL + abase + 32);
#pragma unroll
            for (int mt = 0; mt < 16; mt++) {
                uint32_t bH[4], bL[4];
                uint32_t bbase = (mt * 8 + b_rlane) * PADB2 + kt * 32 + b_seg;
                ldm4(bH, sb + O_BH + bbase);
                ldm4(bL, sb + O_BL + bbase);
                mma_bf16(Dacc[mt], aH + 0, bH[0], bH[1]);
                mma_bf16(Dacc[mt], aH + 0, bL[0], bL[1]);
                mma_bf16(Dacc[mt], aL + 0, bH[0], bH[1]);
                mma_bf16(Dacc[mt], aH + 4, bH[2], bH[3]);
                mma_bf16(Dacc[mt], aH + 4, bL[2], bL[3]);
                mma_bf16(Dacc[mt], aL + 4, bH[2], bH[3]);
            }
        }
        __syncthreads();
    }

    int o0 = wrow + qr;
    float bv0 = bias[o0], bv1 = bias[o0 + 8];

    if (pj == 0) {
#pragma unroll
        for (int mt = 0; mt < 16; mt++) {
            int n = n0 + mt * 8 + qc * 2;
            float v0 = Dacc[mt][0] + bv0;
            float v1 = Dacc[mt][1] + bv0;
            float v2 = Dacc[mt][2] + bv1;
            float v3 = Dacc[mt][3] + bv1;
            u64 r0 = ((u64)b * NN + n) * CI + o0;
            u64 r1 = r0 + CI;
            __nv_bfloat16 h;
            h = __float2bfloat16_rn(v0);
            g_thTH[r0] = __bfloat16_as_ushort(h);
            g_thTL[r0] = __bfloat16_as_ushort(__float2bfloat16_rn(v0 - __bfloat162float(h)));
            h = __float2bfloat16_rn(v2);
            g_thTH[r0 + 8] = __bfloat16_as_ushort(h);
            g_thTL[r0 + 8] = __bfloat16_as_ushort(__float2bfloat16_rn(v2 - __bfloat162float(h)));
            h = __float2bfloat16_rn(v1);
            g_thTH[r1] = __bfloat16_as_ushort(h);
            g_thTL[r1] = __bfloat16_as_ushort(__float2bfloat16_rn(v1 - __bfloat162float(h)));
            h = __float2bfloat16_rn(v3);
            g_thTH[r1 + 8] = __bfloat16_as_ushort(h);
            g_thTL[r1 + 8] = __bfloat16_as_ushort(__float2bfloat16_rn(v3 - __bfloat162float(h)));
        }
    } else {
        uint16_t* dH = (pj == 1) ? g_phiH : g_gHa;
        uint16_t* dL = (pj == 1) ? g_phiL : g_gLa;
#pragma unroll
        for (int mt2 = 0; mt2 < 8; mt2++) {
            int m = blockIdx.x * 32 + mt2 * 4 + qc;
            float p0 = fmaxf(fmaxf(Dacc[mt2][0], Dacc[mt2][1]),
                             fmaxf(Dacc[mt2 + 8][0], Dacc[mt2 + 8][1])) + bv0;
            float p1 = fmaxf(fmaxf(Dacc[mt2][2], Dacc[mt2][3]),
                             fmaxf(Dacc[mt2 + 8][2], Dacc[mt2 + 8][3])) + bv1;
            __nv_bfloat16 h0 = __float2bfloat16_rn(p0);
            __nv_bfloat16 l0 = __float2bfloat16_rn(p0 - __bfloat162float(h0));
            __nv_bfloat16 h1 = __float2bfloat16_rn(p1);
            __nv_bfloat16 l1 = __float2bfloat16_rn(p1 - __bfloat162float(h1));
            u64 i0, i1;
            if (pj == 1) { i0 = ((u64)b * MM + m) * CI + o0; i1 = i0 + 8; }
            else         { i0 = ((u64)b * CI + o0) * MM + m; i1 = i0 + (u64)8 * MM; }
            dH[i0] = __bfloat16_as_ushort(h0); dL[i0] = __bfloat16_as_ushort(l0);
            dH[i1] = __bfloat16_as_ushort(h1); dL[i1] = __bfloat16_as_ushort(l1);
        }
    }
}

// ---------------------------------------------------------------------------
// K2: attention (R12 base). CTA = (b, 128 n). m-chunks of 128, 8 chunks.
// Warp S-tile: 32n x 64m (wa=wid&3 -> n, wh=wid>>2 -> m-half), 2 A-tiles
// share each B fragment. Warp Y-tile: 32ci x 64n, same sharing.
// smem: TH/TL [128][272] | PH/PL phi->P [128][272] | GH/GL g [128][272] |
//       redh[2][128] | inv[128]
// ---------------------------------------------------------------------------
#define PADB 272
#define O_TH 0
#define O_TL 34816
#define O_PH 69632
#define O_PL 104448
#define O_GH 139264
#define O_GL 174080
#define O_RED 208896
#define O_INV 209920
#define ATT_SMEM 210432

__global__ __launch_bounds__(256, 1) void attn_mma_kernel()
{
    extern __shared__ char smem[];
    uint32_t sb = smem_u32(smem);
    int b = blockIdx.y, n0 = blockIdx.x * 128;
    int tid = threadIdx.x;
    int lane = tid & 31, wid = tid >> 5;
    int wa = wid & 3, wh = wid >> 2;
    int qr = lane >> 2, qc = lane & 3;

    auto load_phi = [&](int mc) {
#pragma unroll
        for (int j = 0; j < 8; j++) {
            int id = tid + j * 256;
            int row = id >> 4, seg = id & 15;
            int src = (b * MM + mc * 128 + row) * CI + seg * 8;
            uint32_t d = row * PADB + seg * 16;
            cpa16(sb + O_PH + d, &g_phiH[src]);
            cpa16(sb + O_PL + d, &g_phiL[src]);
        }
    };
    auto load_g = [&](int mc) {
#pragma unroll
        for (int j = 0; j < 8; j++) {
            int id = tid + j * 256;
            int row = id >> 4, seg = id & 15;
            int src = (b * CI + row) * MM + mc * 128 + seg * 8;
            uint32_t d = row * PADB + seg * 16;
            cpa16(sb + O_GH + d, &g_gHa[src]);
            cpa16(sb + O_GL + d, &g_gLa[src]);
        }
    };

    // theta tile [128n][ci] split via cp.async
#pragma unroll
    for (int j = 0; j < 8; j++) {
        int id = tid + j * 256;
        int row = id >> 4, seg = id & 15;
        u64 src = ((u64)b * NN + n0 + row) * CI + seg * 8;
        uint32_t d = row * PADB + seg * 16;
        cpa16(sb + O_TH + d, &g_thTH[src]);
        cpa16(sb + O_TL + d, &g_thTL[src]);
    }
    load_phi(0); CPA_COMMIT();
    load_g(0);   CPA_COMMIT();
    CPA_WAIT0();
    __syncthreads();

    float Yacc[2][8][4];
#pragma unroll
    for (int t = 0; t < 8; t++) {
        Yacc[0][t][0] = Yacc[0][t][1] = Yacc[0][t][2] = Yacc[0][t][3] = 0.f;
        Yacc[1][t][0] = Yacc[1][t][1] = Yacc[1][t][2] = Yacc[1][t][3] = 0.f;
    }
    float rs[2][2] = {{0.f, 0.f}, {0.f, 0.f}};

    uint32_t a_seg = (uint32_t)((lane >> 4) << 4);
    uint32_t b_rl = (uint32_t)(lane & 7);
    uint32_t b_seg = (uint32_t)((lane >> 3) << 4);
    uint32_t aS0 = (uint32_t)(wa * 32 + (lane & 15));        // S A-tile 0 row
    uint32_t aS1 = aS0 + 16;
    uint32_t aY0 = aS0;                                       // Y A-tile rows (ci)
    uint32_t aY1 = aS1;

    for (int mc = 0; mc < 8; mc++) {
        // ---- S = theta . phi^T  (32n x 64m per warp) ----
        float Sacc[2][8][4];
#pragma unroll
        for (int t = 0; t < 8; t++) {
            Sacc[0][t][0] = Sacc[0][t][1] = Sacc[0][t][2] = Sacc[0][t][3] = 0.f;
            Sacc[1][t][0] = Sacc[1][t][1] = Sacc[1][t][2] = Sacc[1][t][3] = 0.f;
        }
#pragma unroll
        for (int kt = 0; kt < 8; kt += 2) {
            uint32_t aH0[8], aL0[8], aH1[8], aL1[8];
            uint32_t ab0 = aS0 * PADB + kt * 32 + a_seg;
            uint32_t ab1 = aS1 * PADB + kt * 32 + a_seg;
            ldm4(aH0 + 0, sb + O_TH + ab0); ldm4(aH0 + 4, sb + O_TH + ab0 + 32);
            ldm4(aL0 + 0, sb + O_TL + ab0); ldm4(aL0 + 4, sb + O_TL + ab0 + 32);
            ldm4(aH1 + 0, sb + O_TH + ab1); ldm4(aH1 + 4, sb + O_TH + ab1 + 32);
            ldm4(aL1 + 0, sb + O_TL + ab1); ldm4(aL1 + 4, sb + O_TL + ab1 + 32);
#pragma unroll
            for (int mt = 0; mt < 8; mt++) {
                uint32_t bH[4], bL[4];
                uint32_t bbase = (wh * 64 + mt * 8 + b_rl) * PADB + kt * 32 + b_seg;
                ldm4(bH, sb + O_PH + bbase);
                ldm4(bL, sb + O_PL + bbase);
                mma_bf16(Sacc[0][mt], aH0 + 0, bH[0], bH[1]);
                mma_bf16(Sacc[0][mt], aH0 + 0, bL[0], bL[1]);
                mma_bf16(Sacc[0][mt], aL0 + 0, bH[0], bH[1]);
                mma_bf16(Sacc[0][mt], aH0 + 4, bH[2], bH[3]);
                mma_bf16(Sacc[0][mt], aH0 + 4, bL[2], bL[3]);
                mma_bf16(Sacc[0][mt], aL0 + 4, bH[2], bH[3]);
                mma_bf16(Sacc[1][mt], aH1 + 0, bH[0], bH[1]);
                mma_bf16(Sacc[1][mt], aH1 + 0, bL[0], bL[1]);
                mma_bf16(Sacc[1][mt], aL1 + 0, bH[0], bH[1]);
                mma_bf16(Sacc[1][mt], aH1 + 4, bH[2], bH[3]);
                mma_bf16(Sacc[1][mt], aH1 + 4, bL[2], bL[3]);
                mma_bf16(Sacc[1][mt], aL1 + 4, bH[2], bH[3]);
            }
        }
        __syncthreads();

        // ---- exp + split -> P [128n][272B] (overwrites phi region) ----
#pragma unroll
        for (int tl = 0; tl < 2; tl++) {
            int r0 = wa * 32 + tl * 16 + qr, r1 = r0 + 8;
#pragma unroll
            for (int mt = 0; mt < 8; mt++) {
                float e0 = exp_s(Sacc[tl][mt][0]);
                float e1 = exp_s(Sacc[tl][mt][1]);
                float e2 = exp_s(Sacc[tl][mt][2]);
                float e3 = exp_s(Sacc[tl][mt][3]);
                rs[tl][0] += e0 + e1; rs[tl][1] += e2 + e3;
                float h0 = __bfloat162float(__float2bfloat16_rn(e0));
                float h1 = __bfloat162float(__float2bfloat16_rn(e1));
                float h2 = __bfloat162float(__float2bfloat16_rn(e2));
                float h3 = __bfloat162float(__float2bfloat16_rn(e3));
                int m2 = (wh * 64 + mt * 8 + qc * 2) * 2;
                uint32_t off0 = r0 * PADB + m2;
                uint32_t off1 = r1 * PADB + m2;
                *(uint32_t*)(smem + O_PH + off0) = pack_bf16x2(h0, h1);
                *(uint32_t*)(smem + O_PH + off1) = pack_bf16x2(h2, h3);
                *(uint32_t*)(smem + O_PL + off0) = pack_bf16x2(e0 - h0, e1 - h1);
                *(uint32_t*)(smem + O_PL + off1) = pack_bf16x2(e2 - h2, e3 - h3);
            }
        }
        CPA_WAIT0();       // g chunk mc complete
        __syncthreads();

        // ---- Y^T += g . P^T  (32ci x 64n per warp) ----
#pragma unroll
        for (int kt = 0; kt < 8; kt += 2) {
            uint32_t aH0[8], aL0[8], aH1[8], aL1[8];
            uint32_t ab0 = aY0 * PADB + kt * 32 + a_seg;
            uint32_t ab1 = aY1 * PADB + kt * 32 + a_seg;
            ldm4(aH0 + 0, sb + O_GH + ab0); ldm4(aH0 + 4, sb + O_GH + ab0 + 32);
            ldm4(aL0 + 0, sb + O_GL + ab0); ldm4(aL0 + 4, sb + O_GL + ab0 + 32);
            ldm4(aH1 + 0, sb + O_GH + ab1); ldm4(aH1 + 4, sb + O_GH + ab1 + 32);
            ldm4(aL1 + 0, sb + O_GL + ab1); ldm4(aL1 + 4, sb + O_GL + ab1 + 32);
#pragma unroll
            for (int nt = 0; nt < 8; nt++) {
                uint32_t bH[4], bL[4];
                uint32_t bbase = (wh * 64 + nt * 8 + b_rl) * PADB + kt * 32 + b_seg;
                ldm4(bH, sb + O_PH + bbase);
                ldm4(bL, sb + O_PL + bbase);
                mma_bf16(Yacc[0][nt], aH0 + 0, bH[0], bH[1]);
                mma_bf16(Yacc[0][nt], aH0 + 0, bL[0], bL[1]);
                mma_bf16(Yacc[0][nt], aL0 + 0, bH[0], bH[1]);
                mma_bf16(Yacc[0][nt], aH0 + 4, bH[2], bH[3]);
                mma_bf16(Yacc[0][nt], aH0 + 4, bL[2], bL[3]);
                mma_bf16(Yacc[0][nt], aL0 + 4, bH[2], bH[3]);
                mma_bf16(Yacc[1][nt], aH1 + 0, bH[0], bH[1]);
                mma_bf16(Yacc[1][nt], aH1 + 0, bL[0], bL[1]);
                mma_bf16(Yacc[1][nt], aL1 + 0, bH[0], bH[1]);
                mma_bf16(Yacc[1][nt], aH1 + 4, bH[2], bH[3]);
                mma_bf16(Yacc[1][nt], aH1 + 4, bL[2], bL[3]);
                mma_bf16(Yacc[1][nt], aL1 + 4, bH[2], bH[3]);
            }
        }
        __syncthreads();

        if (mc < 7) {
            load_phi(mc + 1); CPA_COMMIT();
            load_g(mc + 1);   CPA_COMMIT();
            CPA_WAIT1();
            __syncthreads();
        }
    }

    // ---- rowsums: shfl over qc, combine wh-halves, invert ----
    float* redh = (float*)(smem + O_RED);
#pragma unroll
    for (int tl = 0; tl < 2; tl++) {
        rs[tl][0] += __shfl_xor_sync(0xffffffffu, rs[tl][0], 1);
        rs[tl][0] += __shfl_xor_sync(0xffffffffu, rs[tl][0], 2);
        rs[tl][1] += __shfl_xor_sync(0xffffffffu, rs[tl][1], 1);
        rs[tl][1] += __shfl_xor_sync(0xffffffffu, rs[tl][1], 2);
        if (qc == 0) {
            redh[wh * 128 + wa * 32 + tl * 16 + qr]     = rs[tl][0];
            redh[wh * 128 + wa * 32 + tl * 16 + qr + 8] = rs[tl][1];
        }
    }
    __syncthreads();
    float* invs = (float*)(smem + O_INV);
    if (tid < 128) invs[tid] = 1.0f / (redh[tid] + redh[128 + tid]);
    __syncthreads();

    // ---- epilogue: normalize, split, store y^T [b][n][ci] ----
#pragma unroll
    for (int tl = 0; tl < 2; tl++) {
        int ci0 = wa * 32 + tl * 16 + qr;
#pragma unroll
        for (int nt = 0; nt < 8; nt++) {
            int nl2 = wh * 64 + nt * 8 + qc * 2;
            float in0 = invs[nl2], in1 = invs[nl2 + 1];
            float y00 = Yacc[tl][nt][0] * in0;
            float y01 = Yacc[tl][nt][1] * in1;
            float y10 = Yacc[tl][nt][2] * in0;
            float y11 = Yacc[tl][nt][3] * in1;
            u64 r0 = ((u64)b * NN + n0 + nl2) * CI + ci0;
            u64 r1 = r0 + CI;
            __nv_bfloat16 h;
            h = __float2bfloat16_rn(y00);
            g_yTH[r0] = __bfloat16_as_ushort(h);
            g_yTL[r0] = __bfloat16_as_ushort(__float2bfloat16_rn(y00 - __bfloat162float(h)));
            h = __float2bfloat16_rn(y10);
            g_yTH[r0 + 8] = __bfloat16_as_ushort(h);
            g_yTL[r0 + 8] = __bfloat16_as_ushort(__float2bfloat16_rn(y10 - __bfloat162float(h)));
            h = __float2bfloat16_rn(y01);
            g_yTH[r1] = __bfloat16_as_ushort(h);
            g_yTL[r1] = __bfloat16_as_ushort(__float2bfloat16_rn(y01 - __bfloat162float(h)));
            h = __float2bfloat16_rn(y11);
            g_yTH[r1 + 8] = __bfloat16_as_ushort(h);
            g_yTL[r1 + 8] = __bfloat16_as_ushort(__float2bfloat16_rn(y11 - __bfloat162float(h)));
        }
    }
}

// ---------------------------------------------------------------------------
// wproj_mma: K=128 in 2 chunks of 64; 2 CTAs/SM. (validated R12)
// ---------------------------------------------------------------------------
__global__ __launch_bounds__(256, 2) void wproj_mma_kernel(
    const float* __restrict__ bias)
{
    extern __shared__ char smem[];
    uint32_t sb = smem_u32(smem);
    const uint32_t O_AH = 0, O_AL = TILE2, O_BH = 2 * TILE2, O_BL = 3 * TILE2;
    int b = blockIdx.z, o0 = blockIdx.y * 128, n0 = blockIdx.x * 128;
    int tid = threadIdx.x, lane = tid & 31, wid = tid >> 5;
    int wrow = wid * 16, qr = lane >> 2, qc = lane & 3;

    uint32_t a_row = (uint32_t)(wrow + (lane & 15));
    uint32_t a_seg = (uint32_t)((lane >> 4) << 4);
    uint32_t b_rlane = (uint32_t)(lane & 7);
    uint32_t b_seg = (uint32_t)((lane >> 3) << 4);

    float Dacc[16][4];
#pragma unroll
    for (int t = 0; t < 16; t++) { Dacc[t][0] = Dacc[t][1] = Dacc[t][2] = Dacc[t][3] = 0.f; }

    for (int kc = 0; kc < 2; kc++) {
#pragma unroll
        for (int j = 0; j < 4; j++) {
            int id = tid + j * 256;
            int row = id >> 3, seg = id & 7;
            uint32_t d = row * PADB2 + seg * 16;
            int wsrc = 98304 + (o0 + row) * 128 + kc * 64 + seg * 8;
            u64 ysrc = ((u64)b * NN + n0 + row) * CI + kc * 64 + seg * 8;
            cpa16(sb + O_AH + d, &g_wsH[wsrc]);
            cpa16(sb + O_AL + d, &g_wsL[wsrc]);
            cpa16(sb + O_BH + d, &g_yTH[ysrc]);
            cpa16(sb + O_BL + d, &g_yTL[ysrc]);
        }
        CPA_COMMIT(); CPA_WAIT0();
        __syncthreads();

#pragma unroll
        for (int kt = 0; kt < 4; kt += 2) {
            uint32_t aH[8], aL[8];
            uint32_t abase = a_row * PADB2 + kt * 32 + a_seg;
            ldm4(aH + 0, sb + O_AH + abase);
            ldm4(aH + 4, sb + O_AH + abase + 32);
            ldm4(aL + 0, sb + O_AL + abase);
            ldm4(aL + 4, sb + O_AL + abase + 32);
#pragma unroll
            for (int mt = 0; mt < 16; mt++) {
                uint32_t bH[4], bL[4];
                uint32_t bbase = (mt * 8 + b_rlane) * PADB2 + kt * 32 + b_seg;
                ldm4(bH, sb + O_BH + bbase);
                ldm4(bL, sb + O_BL + bbase);
                mma_bf16(Dacc[mt], aH + 0, bH[0], bH[1]);
                mma_bf16(Dacc[mt], aH + 0, bL[0], bL[1]);
                mma_bf16(Dacc[mt], aL + 0, bH[0], bH[1]);
                mma_bf16(Dacc[mt], aH + 4, bH[2], bH[3]);
                mma_bf16(Dacc[mt], aH + 4, bL[2], bL[3]);
                mma_bf16(Dacc[mt], aL + 4, bH[2], bH[3]);
            }
        }
        __syncthreads();
    }

    int og0 = o0 + wrow + qr, og1 = og0 + 8;
    float bv0 = bias[og0], bv1 = bias[og1];
    float* ob = g_z + (u64)b * CC * NN;
    float s0 = 0.f, q0 = 0.f, s1 = 0.f, q1 = 0.f;
#pragma unroll
    for (int mt = 0; mt < 16; mt++) {
        int n = n0 + mt * 8 + qc * 2;
        float v0 = Dacc[mt][0] + bv0, v1 = Dacc[mt][1] + bv0;
        float v2 = Dacc[mt][2] + bv1, v3 = Dacc[mt][3] + bv1;
        *(float2*)&ob[(u64)og0 * NN + n] = make_float2(v0, v1);
        *(float2*)&ob[(u64)og1 * NN + n] = make_float2(v2, v3);
        s0 += v0 + v1; q0 += v0 * v0 + v1 * v1;
        s1 += v2 + v3; q1 += v2 * v2 + v3 * v3;
    }
    s0 += __shfl_xor_sync(0xffffffffu, s0, 1);
    s0 += __shfl_xor_sync(0xffffffffu, s0, 2);
    q0 += __shfl_xor_sync(0xffffffffu, q0, 1);
    q0 += __shfl_xor_sync(0xffffffffu, q0, 2);
    s1 += __shfl_xor_sync(0xffffffffu, s1, 1);
    s1 += __shfl_xor_sync(0xffffffffu, s1, 2);
    q1 += __shfl_xor_sync(0xffffffffu, q1, 1);
    q1 += __shfl_xor_sync(0xffffffffu, q1, 2);
    if (qc == 0) {
        int slot = b * 32 + blockIdx.x;
        g_psum  [og0 * 256 + slot] = s0;
        g_psumsq[og0 * 256 + slot] = q0;
        g_psum  [og1 * 256 + slot] = s1;
        g_psumsq[og1 * 256 + slot] = q1;
    }
}

// ---------------------------------------------------------------------------
__global__ void bnfin_kernel(const float* __restrict__ gamma,
                             const float* __restrict__ beta)
{
    int c = threadIdx.x;
    float s = 0.f, s2 = 0.f;
    for (int j = 0; j < 256; j++) { s += g_psum[c * 256 + j]; s2 += g_psumsq[c * 256 + j]; }
    const float inv_n = 1.0f / 32768.0f;
    float mean = s * inv_n;
    float var  = s2 * inv_n - mean * mean;
    float inv  = rsqrtf(var + 1e-5f);
    float a = gamma[c] * inv;
    g_bna[c] = a;
    g_bnb[c] = beta[c] - mean * a;
}

// ---------------------------------------------------------------------------
__global__ __launch_bounds__(256) void final_kernel(
    const float* __restrict__ x, float* __restrict__ out)
{
    int idx = blockIdx.x * 256 + threadIdx.x;
    u64 e = (u64)idx << 2;
    int c = (int)((e >> 12) & 255);
    float4 xv = *(const float4*)(x + e);
    float4 zv = *((const float4*)g_z + idx);
    float a = g_bna[c], bb = g_bnb[c];
    float4 o;
    o.x = fmaf(zv.x, a, bb) + xv.x;
    o.y = fmaf(zv.y, a, bb) + xv.y;
    o.z = fmaf(zv.z, a, bb) + xv.z;
    o.w = fmaf(zv.w, a, bb) + xv.w;
    *(float4*)(out + e) = o;
}

// ---------------------------------------------------------------------------
extern "C" void kernel_launch(void* const* d_in, const int* in_sizes, int n_in,
                              void* d_out, int out_size)
{
    const float* x     = (const float*)d_in[0];
    const float* tw    = (const float*)d_in[1];
    const float* tb    = (const float*)d_in[2];
    const float* pw    = (const float*)d_in[3];
    const float* pb    = (const float*)d_in[4];
    const float* gw    = (const float*)d_in[5];
    const float* gbv   = (const float*)d_in[6];
    const float* Ww    = (const float*)d_in[7];
    const float* Wb    = (const float*)d_in[8];
    const float* gamma = (const float*)d_in[9];
    const float* beta  = (const float*)d_in[10];
    float* out = (float*)d_out;

    cudaFuncSetAttribute(attn_mma_kernel,
                         cudaFuncAttributeMaxDynamicSharedMemorySize, ATT_SMEM);
    cudaFuncSetAttribute(proj_mma_kernel,
                         cudaFuncAttributeMaxDynamicSharedMemorySize, PRJ_SMEM);
    cudaFuncSetAttribute(wproj_mma_kernel,
                         cudaFuncAttributeMaxDynamicSharedMemorySize, PRJ_SMEM);

    xsplit_kernel<<<dim3(128, 8, 8), 256>>>(x);
    wsplit_kernel<<<512, 256>>>(tw, pw, gw, Ww);
    proj_mma_kernel<<<dim3(32, 3, 8), 256, PRJ_SMEM>>>(tb, pb, gbv);
    attn_mma_kernel<<<dim3(32, 8), 256, ATT_SMEM>>>();
    wproj_mma_kernel<<<dim3(32, 2, 8), 256, PRJ_SMEM>>>(Wb);
    bnfin_kernel<<<1, 256>>>(gamma, beta);
    final_kernel<<<8192, 256>>>(x, out);
}